// round 16
// baseline (speedup 1.0000x reference)
#include <cuda_runtime.h>
#include <cuda_bf16.h>
#include <cstdint>
#include <cstddef>

// ---------------- problem constants ----------------
#define NU 20000
#define NV 20000
#define NE 320000
#define BN_EPS 1e-5f
#define NEG_BIG (-3.402823466e+38f)
#define DK 896

typedef __nv_bfloat16 bf;

// ---------------- scratch arena ----------------
static constexpr size_t AL(size_t x) { return (x + 255) & ~(size_t)255; }
static constexpr size_t SZ_AH   = AL((size_t)NU * DK * 2);
static constexpr size_t SZ_XE   = AL((size_t)NE * 64 * 2);
static constexpr size_t SZ_XT   = AL((size_t)NU * 256 * 2);
static constexpr size_t SZ_WTU  = AL((size_t)256 * DK * 2);
static constexpr size_t SZ_WTE  = AL((size_t)64 * 576 * 2);
static constexpr size_t SZ_P    = AL((size_t)NU * 64 * 4);
static constexpr size_t SZ_L    = AL((size_t)NU * 4);
static constexpr size_t SZ_OFF  = AL((size_t)(NU + 1) * 4);
static constexpr size_t SZ_EID  = AL((size_t)NE * 4);
static constexpr size_t SZ_RED  = 256;
static constexpr size_t SZ_STAT = 16384;

static constexpr size_t OFF_AHU  = 0;
static constexpr size_t OFF_ALU  = OFF_AHU + SZ_AH;
static constexpr size_t OFF_AHV  = OFF_ALU + SZ_AH;
static constexpr size_t OFF_ALV  = OFF_AHV + SZ_AH;
static constexpr size_t OFF_XEH  = OFF_ALV + SZ_AH;
static constexpr size_t OFF_XEL  = OFF_XEH + SZ_XE;
static constexpr size_t OFF_XUTH = OFF_XEL + SZ_XE;
static constexpr size_t OFF_XUTL = OFF_XUTH + SZ_XT;
static constexpr size_t OFF_XVTH = OFF_XUTL + SZ_XT;
static constexpr size_t OFF_XVTL = OFF_XVTH + SZ_XT;
static constexpr size_t OFF_WTUH = OFF_XVTL + SZ_XT;
static constexpr size_t OFF_WTUL = OFF_WTUH + SZ_WTU;
static constexpr size_t OFF_WTVH = OFF_WTUL + SZ_WTU;
static constexpr size_t OFF_WTVL = OFF_WTVH + SZ_WTU;
static constexpr size_t OFF_WTEH = OFF_WTVL + SZ_WTU;
static constexpr size_t OFF_WTEL = OFF_WTEH + SZ_WTE;
static constexpr size_t OFF_PU   = OFF_WTEL + SZ_WTE;
static constexpr size_t OFF_PV   = OFF_PU + SZ_P;
static constexpr size_t OFF_LU   = OFF_PV + SZ_P;
static constexpr size_t OFF_LV   = OFF_LU + SZ_L;
static constexpr size_t OFF_WU   = OFF_LV + SZ_L;
static constexpr size_t OFF_WV   = OFF_WU + SZ_L;
static constexpr size_t OFF_CNTU = OFF_WV + SZ_L;
static constexpr size_t OFF_CNTV = OFF_CNTU + SZ_L;
static constexpr size_t OFF_OFFU = OFF_CNTV + SZ_L;
static constexpr size_t OFF_OFFV = OFF_OFFU + SZ_OFF;
static constexpr size_t OFF_CURU = OFF_OFFV + SZ_OFF;
static constexpr size_t OFF_CURV = OFF_CURU + SZ_L;
static constexpr size_t OFF_EIDU = OFF_CURV + SZ_L;
static constexpr size_t OFF_EIDV = OFF_EIDU + SZ_EID;
static constexpr size_t OFF_RED  = OFF_EIDV + SZ_EID;
static constexpr size_t OFF_STAT = OFF_RED + SZ_RED;
static constexpr size_t SCRATCH_TOTAL = OFF_STAT + SZ_STAT;

__device__ __align__(1024) unsigned char g_scratch[SCRATCH_TOTAL];

__device__ __forceinline__ float* SF(size_t off) { return (float*)(g_scratch + off); }
__device__ __forceinline__ int*   SI(size_t off) { return (int*)(g_scratch + off); }

// ---------------- helpers ----------------
__device__ __forceinline__ uint32_t s2u(const void* p) {
    uint32_t a;
    asm("{ .reg .u64 t; cvta.to.shared.u64 t, %1; cvt.u32.u64 %0, t; }" : "=r"(a) : "l"(p));
    return a;
}
__device__ __forceinline__ void cpa16(uint32_t dst, const void* src, int srcsz) {
    asm volatile("cp.async.cg.shared.global [%0], [%1], 16, %2;"
        :: "r"(dst), "l"(src), "r"(srcsz) : "memory");
}
#define CP_COMMIT() asm volatile("cp.async.commit_group;" ::: "memory")
#define CP_WAIT1()  asm volatile("cp.async.wait_group 1;" ::: "memory")
#define CP_WAIT0()  asm volatile("cp.async.wait_group 0;" ::: "memory")

__device__ __forceinline__ void ldsm4(uint32_t& r0, uint32_t& r1, uint32_t& r2, uint32_t& r3,
                                      uint32_t addr) {
    asm volatile("ldmatrix.sync.aligned.m8n8.x4.shared.b16 {%0,%1,%2,%3}, [%4];"
        : "=r"(r0), "=r"(r1), "=r"(r2), "=r"(r3) : "r"(addr));
}
__device__ __forceinline__ void mma_bf16(float* c,
        uint32_t a0, uint32_t a1, uint32_t a2, uint32_t a3, uint32_t b0, uint32_t b1) {
    asm volatile("mma.sync.aligned.m16n8k16.row.col.f32.bf16.bf16.f32 "
        "{%0,%1,%2,%3}, {%4,%5,%6,%7}, {%8,%9}, {%0,%1,%2,%3};"
        : "+f"(c[0]), "+f"(c[1]), "+f"(c[2]), "+f"(c[3])
        : "r"(a0), "r"(a1), "r"(a2), "r"(a3), "r"(b0), "r"(b1));
}
__device__ __forceinline__ void bsplit(float v, bf& h, bf& l) {
    h = __float2bfloat16(v);
    l = __float2bfloat16(v - __bfloat162float(h));
}
__device__ __forceinline__ uint32_t swz(uint32_t row, uint32_t seg) {
    return (row << 6) | (((seg ^ (row >> 1)) & 3u) << 4);
}
__device__ __forceinline__ float4 f4add(float4 a, float4 b) {
    return make_float4(a.x + b.x, a.y + b.y, a.z + b.z, a.w + b.w);
}
__device__ __forceinline__ float4 f4max(float4 a, float4 b) {
    return make_float4(fmaxf(a.x, b.x), fmaxf(a.y, b.y), fmaxf(a.z, b.z), fmaxf(a.w, b.w));
}
__device__ __forceinline__ float4 f4scale(float4 a, float s) {
    return make_float4(a.x * s, a.y * s, a.z * s, a.w * s);
}

// ---------------- init ----------------
__global__ void init_k() {
    int i = blockIdx.x * blockDim.x + threadIdx.x;
    if (i < NU) { SI(OFF_CNTU)[i] = 0; SI(OFF_CNTV)[i] = 0; }
    if (i < 1152) SF(OFF_STAT)[i] = 0.f;
}

// ---------------- attention ----------------
__global__ void logits_k(const float* __restrict__ xus, const float* __restrict__ xvs,
                         const float* __restrict__ attn_u2v, const float* __restrict__ attn_v2u) {
    int w = (blockIdx.x * blockDim.x + threadIdx.x) >> 5;
    int lane = threadIdx.x & 31;
    if (w >= NU + NV) return;
    const float* x; const float* a; float* out; int r;
    if (w < NU) { x = xus; a = attn_u2v; out = SF(OFF_LU); r = w; }
    else        { x = xvs; a = attn_v2u; out = SF(OFF_LV); r = w - NU; }
    float s = 0.f;
    const float* xr = x + (size_t)r * 256;
    #pragma unroll
    for (int k = lane; k < 256; k += 32) s += xr[k] * a[k];
    #pragma unroll
    for (int o = 16; o; o >>= 1) s += __shfl_down_sync(0xffffffffu, s, o);
    if (lane == 0) out[r] = s;
}

__global__ void softmax_reduce_k() {
    const float* l = blockIdx.x ? SF(OFF_LV) : SF(OFF_LU);
    __shared__ float sh[1024];
    int t = threadIdx.x;
    float m = NEG_BIG;
    for (int i = t; i < NU; i += 1024) m = fmaxf(m, l[i]);
    sh[t] = m; __syncthreads();
    for (int s = 512; s; s >>= 1) { if (t < s) sh[t] = fmaxf(sh[t], sh[t + s]); __syncthreads(); }
    float mx = sh[0]; __syncthreads();
    float su = 0.f;
    for (int i = t; i < NU; i += 1024) su += expf(l[i] - mx);
    sh[t] = su; __syncthreads();
    for (int s = 512; s; s >>= 1) { if (t < s) sh[t] += sh[t + s]; __syncthreads(); }
    if (t == 0) { float* red = SF(OFF_RED); red[blockIdx.x * 2] = mx; red[blockIdx.x * 2 + 1] = sh[0]; }
}

__global__ void weights_k() {
    int i = blockIdx.x * blockDim.x + threadIdx.x;
    if (i >= NU) return;
    float* red = SF(OFF_RED);
    SF(OFF_WU)[i] = expf(SF(OFF_LU)[i] - red[0]) / red[1];
    SF(OFF_WV)[i] = expf(SF(OFF_LV)[i] - red[2]) / red[3];
}

// ---------------- CSR build ----------------
__global__ void hist_k(const int* __restrict__ row_v2u, const int* __restrict__ col_u2v) {
    int i = blockIdx.x * blockDim.x + threadIdx.x;
    if (i < NE) atomicAdd(&SI(OFF_CNTU)[row_v2u[i]], 1);
    else if (i < 2 * NE) atomicAdd(&SI(OFF_CNTV)[col_u2v[i - NE]], 1);
}

__global__ void scan_k() {
    const int* cnt = blockIdx.x ? SI(OFF_CNTV) : SI(OFF_CNTU);
    int* off = blockIdx.x ? SI(OFF_OFFV) : SI(OFF_OFFU);
    int* cur = blockIdx.x ? SI(OFF_CURV) : SI(OFF_CURU);
    __shared__ int sh[1024];
    __shared__ int carry;
    int t = threadIdx.x;
    if (t == 0) carry = 0;
    __syncthreads();
    for (int base = 0; base < NU; base += 1024) {
        int i = base + t;
        int v = (i < NU) ? cnt[i] : 0;
        sh[t] = v; __syncthreads();
        for (int s = 1; s < 1024; s <<= 1) {
            int tv = (t >= s) ? sh[t - s] : 0;
            __syncthreads();
            sh[t] += tv;
            __syncthreads();
        }
        int exc = sh[t] - v;
        if (i < NU) { off[i] = carry + exc; cur[i] = carry + exc; }
        __syncthreads();
        if (t == 0) carry += sh[1023];
        __syncthreads();
    }
    if (t == 0) off[NU] = carry;
}

__global__ void scatter_k(const int* __restrict__ row_v2u, const int* __restrict__ col_u2v) {
    int i = blockIdx.x * blockDim.x + threadIdx.x;
    if (i < NE) {
        int p = atomicAdd(&SI(OFF_CURU)[row_v2u[i]], 1);
        SI(OFF_EIDU)[p] = i;
    } else if (i < 2 * NE) {
        int e = i - NE;
        int p = atomicAdd(&SI(OFF_CURV)[col_u2v[e]], 1);
        SI(OFF_EIDV)[p] = e;
    }
}

// ---------------- bf16 splits ----------------
__global__ void split_k(const float* __restrict__ x, bf* __restrict__ hi,
                        bf* __restrict__ lo, size_t n) {
    size_t stride = (size_t)gridDim.x * blockDim.x;
    for (size_t i = blockIdx.x * (size_t)blockDim.x + threadIdx.x; i < n; i += stride) {
        bf h, l;
        bsplit(x[i], h, l);
        hi[i] = h; lo[i] = l;
    }
}

__global__ void tsplit_k(const float* __restrict__ W, int K, int N,
                         bf* __restrict__ hi, bf* __restrict__ lo) {
    int total = K * N;
    int stride = gridDim.x * blockDim.x;
    for (int i = blockIdx.x * blockDim.x + threadIdx.x; i < total; i += stride) {
        int nn = i / K, kk = i - nn * K;
        bf h, l;
        bsplit(W[(size_t)kk * N + nn], h, l);
        hi[i] = h; lo[i] = l;
    }
}

// ---------------- aggregation: float4 gathers, explicit 4-deep unroll ----------------
#define AGG_BT 128
__global__ __launch_bounds__(256) void agg_k(
        const int* __restrict__ off0, const int* __restrict__ eids0,
        const int* __restrict__ soe0, const float* __restrict__ w0,
        const float* __restrict__ xs0, const float* __restrict__ xe0,
        const float* __restrict__ xt0, bf* __restrict__ hh0, bf* __restrict__ hl0,
        const int* __restrict__ off1, const int* __restrict__ eids1,
        const int* __restrict__ soe1, const float* __restrict__ w1,
        const float* __restrict__ xs1, const float* __restrict__ xe1,
        const float* __restrict__ xt1, bf* __restrict__ hh1, bf* __restrict__ hl1) {
    __shared__ int   s_src[AGG_BT];
    __shared__ float s_w[AGG_BT];
    __shared__ int   s_eid[AGG_BT];
    __shared__ float4 rs[4][64], rm[4][64];
    __shared__ float4 res[4][16], rem[4][16];

    int u = blockIdx.x;
    bool second = (u >= NU);
    if (second) u -= NU;
    const int* off = second ? off1 : off0;
    const int* eids = second ? eids1 : eids0;
    const int* soe = second ? soe1 : soe0;
    const float* w = second ? w1 : w0;
    const float* xsrc = second ? xs1 : xs0;
    const float* xe = second ? xe1 : xe0;
    const float* xtgt = second ? xt1 : xt0;
    bf* hhi = second ? hh1 : hh0;
    bf* hlo = second ? hl1 : hl0;

    int t = threadIdx.x;
    int slot = t >> 6, q = t & 63;
    int slot_e = t >> 4, qe = t & 15;
    int s = off[u], e = off[u + 1];
    int deg = e - s;

    float4 sum4 = make_float4(0.f, 0.f, 0.f, 0.f);
    float4 mx4 = make_float4(NEG_BIG, NEG_BIG, NEG_BIG, NEG_BIG);
    float4 es4 = make_float4(0.f, 0.f, 0.f, 0.f);
    float4 em4 = make_float4(NEG_BIG, NEG_BIG, NEG_BIG, NEG_BIG);

    for (int base = s; base < e; base += AGG_BT) {
        int cnt = min(AGG_BT, e - base);
        __syncthreads();
        if (t < cnt) {
            int eid = __ldg(&eids[base + t]);
            s_eid[t] = eid;
            int sc = __ldg(&soe[eid]);
            s_src[t] = sc;
            s_w[t] = __ldg(&w[sc]);
        }
        __syncthreads();
        // ---- message gather: 4 independent LDG.128 chains per iteration ----
        {
            int j = slot;
            for (; j + 12 < cnt; j += 16) {
                float w0_ = s_w[j], w1_ = s_w[j + 4], w2_ = s_w[j + 8], w3_ = s_w[j + 12];
                float4 v0 = __ldg((const float4*)(xsrc + (size_t)s_src[j] * 256) + q);
                float4 v1 = __ldg((const float4*)(xsrc + (size_t)s_src[j + 4] * 256) + q);
                float4 v2 = __ldg((const float4*)(xsrc + (size_t)s_src[j + 8] * 256) + q);
                float4 v3 = __ldg((const float4*)(xsrc + (size_t)s_src[j + 12] * 256) + q);
                v0 = f4scale(v0, w0_); v1 = f4scale(v1, w1_);
                v2 = f4scale(v2, w2_); v3 = f4scale(v3, w3_);
                sum4 = f4add(sum4, v0); mx4 = f4max(mx4, v0);
                sum4 = f4add(sum4, v1); mx4 = f4max(mx4, v1);
                sum4 = f4add(sum4, v2); mx4 = f4max(mx4, v2);
                sum4 = f4add(sum4, v3); mx4 = f4max(mx4, v3);
            }
            for (; j < cnt; j += 4) {
                float4 v = f4scale(__ldg((const float4*)(xsrc + (size_t)s_src[j] * 256) + q), s_w[j]);
                sum4 = f4add(sum4, v);
                mx4 = f4max(mx4, v);
            }
        }
        // ---- edge-feature gather (threads 0..63), same unroll ----
        if (t < 64) {
            int j = slot_e;
            for (; j + 12 < cnt; j += 16) {
                float4 v0 = __ldg((const float4*)(xe + (size_t)s_eid[j] * 64) + qe);
                float4 v1 = __ldg((const float4*)(xe + (size_t)s_eid[j + 4] * 64) + qe);
                float4 v2 = __ldg((const float4*)(xe + (size_t)s_eid[j + 8] * 64) + qe);
                float4 v3 = __ldg((const float4*)(xe + (size_t)s_eid[j + 12] * 64) + qe);
                es4 = f4add(es4, v0); em4 = f4max(em4, v0);
                es4 = f4add(es4, v1); em4 = f4max(em4, v1);
                es4 = f4add(es4, v2); em4 = f4max(em4, v2);
                es4 = f4add(es4, v3); em4 = f4max(em4, v3);
            }
            for (; j < cnt; j += 4) {
                float4 v = __ldg((const float4*)(xe + (size_t)s_eid[j] * 64) + qe);
                es4 = f4add(es4, v);
                em4 = f4max(em4, v);
            }
        }
    }
    rs[slot][q] = sum4;
    rm[slot][q] = mx4;
    if (t < 64) { res[slot_e][qe] = es4; rem[slot_e][qe] = em4; }
    __syncthreads();

    float inv = 1.f / (float)(deg > 0 ? deg : 1);
    size_t base = (size_t)u * DK;
    {
        bf h, l;
        bsplit(__ldg(&xtgt[(size_t)u * 256 + t]), h, l);
        hhi[base + t] = h; hlo[base + t] = l;
    }
    if (t < 64) {
        float4 S = f4add(f4add(rs[0][t], rs[1][t]), f4add(rs[2][t], rs[3][t]));
        float4 X = f4max(f4max(rm[0][t], rm[1][t]), f4max(rm[2][t], rm[3][t]));
        float sm[4] = {S.x * inv, S.y * inv, S.z * inv, S.w * inv};
        float xm[4] = {X.x, X.y, X.z, X.w};
        #pragma unroll
        for (int i = 0; i < 4; i++) {
            if (deg == 0) xm[i] = 0.f;
            bf h, l;
            bsplit(sm[i], h, l);
            hhi[base + 256 + 4 * t + i] = h; hlo[base + 256 + 4 * t + i] = l;
            bsplit(xm[i], h, l);
            hhi[base + 512 + 4 * t + i] = h; hlo[base + 512 + 4 * t + i] = l;
        }
    }
    if (t < 16) {
        float4 S = f4add(f4add(res[0][t], res[1][t]), f4add(res[2][t], res[3][t]));
        float4 X = f4max(f4max(rem[0][t], rem[1][t]), f4max(rem[2][t], rem[3][t]));
        float sm[4] = {S.x * inv, S.y * inv, S.z * inv, S.w * inv};
        float xm[4] = {X.x, X.y, X.z, X.w};
        #pragma unroll
        for (int i = 0; i < 4; i++) {
            if (deg == 0) xm[i] = 0.f;
            bf h, l;
            bsplit(sm[i], h, l);
            hhi[base + 768 + 4 * t + i] = h; hlo[base + 768 + 4 * t + i] = l;
            bsplit(xm[i], h, l);
            hhi[base + 832 + 4 * t + i] = h; hlo[base + 832 + 4 * t + i] = l;
        }
    }
}

// ---------------- bf16 3-pass mma GEMM (2-stage, 3 CTAs/SM — best measured) ----------------
#define GROWS 384
#define GSTAGE (GROWS * 64)
__global__ __launch_bounds__(256, 3) void gemm_bf3(
        const bf* __restrict__ Ah0, const bf* __restrict__ Al0,
        const bf* __restrict__ Bh0, const bf* __restrict__ Bl0, float* __restrict__ C0,
        const bf* __restrict__ Ah1, const bf* __restrict__ Al1,
        const bf* __restrict__ Bh1, const bf* __restrict__ Bl1, float* __restrict__ C1,
        int lda, int ldb, int ldc, int M, int Kt,
        const float* __restrict__ fu, const float* __restrict__ fv,
        const int* __restrict__ erow, const int* __restrict__ ecol,
        float* __restrict__ gsum0, float* __restrict__ gssq0,
        float* __restrict__ gsum1, float* __restrict__ gssq1) {
    extern __shared__ unsigned char smemraw[];
    constexpr int NF = 4;
    constexpr int NITER = (GROWS * 4) / 256;

    int sel = blockIdx.z;
    const bf* Ah = sel ? Ah1 : Ah0;
    const bf* Al = sel ? Al1 : Al0;
    const bf* Bh = sel ? Bh1 : Bh0;
    const bf* Bl = sel ? Bl1 : Bl0;
    float* C = sel ? C1 : C0;
    float* gsum = sel ? gsum1 : gsum0;
    float* gssq = sel ? gssq1 : gssq0;

    int tid = threadIdx.x;
    int lane = tid & 31, warp = tid >> 5;
    int wm = warp >> 1, wn = warp & 1;
    int m0 = blockIdx.x * 128;
    int nb0 = blockIdx.y * 64;
    int g = lane >> 2, t4 = lane & 3;
    uint32_t sbase = s2u(smemraw);

    float acc[2][NF][4];
    #pragma unroll
    for (int a = 0; a < 2; a++)
        #pragma unroll
        for (int b = 0; b < NF; b++)
            #pragma unroll
            for (int q = 0; q < 4; q++) acc[a][b][q] = 0.f;

    int nch = Kt >> 5;

    uint32_t a_row = (uint32_t)(wm * 32 + (lane & 15));
    uint32_t a_sg  = (uint32_t)(lane >> 4);
    uint32_t b_row = (uint32_t)(256 + wn * 32 + (lane & 7) + ((lane >> 4) << 3));
    uint32_t b_sg  = (uint32_t)((lane >> 3) & 1);

    auto issue = [&](int c) {
        uint32_t stg = sbase + (uint32_t)(c & 1) * GSTAGE;
        int kel = c * 32;
        #pragma unroll
        for (int i = 0; i < NITER; i++) {
            int task = tid + 256 * i;
            uint32_t row = (uint32_t)(task >> 2);
            uint32_t seg = (uint32_t)(task & 3);
            const bf* src;
            int sz = 16;
            if (row < 256) {
                int r = row & 127;
                int gr = m0 + r;
                const bf* Abase = (row < 128) ? Ah : Al;
                if (gr >= M) { gr = M - 1; sz = 0; }
                src = Abase + (size_t)gr * lda + kel + seg * 8;
            } else {
                uint32_t r2 = row - 256;
                int rb = r2 & 63;
                const bf* Bbase = (r2 < 64) ? Bh : Bl;
                src = Bbase + (size_t)(nb0 + rb) * ldb + kel + seg * 8;
            }
            cpa16(stg + swz(row, seg), src, sz);
        }
        CP_COMMIT();
    };

    issue(0);
    for (int c = 0; c < nch; c++) {
        if (c + 1 < nch) { issue(c + 1); CP_WAIT1(); }
        else             { CP_WAIT0(); }
        __syncthreads();
        uint32_t stg = sbase + (uint32_t)(c & 1) * GSTAGE;
        #pragma unroll
        for (int ks = 0; ks < 2; ks++) {
            uint32_t ah[2][4], al[2][4];
            #pragma unroll
            for (int mt = 0; mt < 2; mt++) {
                uint32_t row = a_row + (uint32_t)(mt * 16);
                uint32_t ad = stg + swz(row, a_sg + 2u * (uint32_t)ks);
                ldsm4(ah[mt][0], ah[mt][1], ah[mt][2], ah[mt][3], ad);
                ldsm4(al[mt][0], al[mt][1], al[mt][2], al[mt][3], ad + 8192u);
            }
            #pragma unroll
            for (int p = 0; p < 2; p++) {
                uint32_t row = b_row + (uint32_t)(p * 16);
                uint32_t bd = stg + swz(row, b_sg + 2u * (uint32_t)ks);
                uint32_t bh0, bh1, bh2, bh3, bl0, bl1, bl2, bl3;
                ldsm4(bh0, bh1, bh2, bh3, bd);
                ldsm4(bl0, bl1, bl2, bl3, bd + 4096u);
                mma_bf16(acc[0][2 * p],     ah[0][0], ah[0][1], ah[0][2], ah[0][3], bh0, bh1);
                mma_bf16(acc[0][2 * p + 1], ah[0][0], ah[0][1], ah[0][2], ah[0][3], bh2, bh3);
                mma_bf16(acc[1][2 * p],     ah[1][0], ah[1][1], ah[1][2], ah[1][3], bh0, bh1);
                mma_bf16(acc[1][2 * p + 1], ah[1][0], ah[1][1], ah[1][2], ah[1][3], bh2, bh3);
                mma_bf16(acc[0][2 * p],     ah[0][0], ah[0][1], ah[0][2], ah[0][3], bl0, bl1);
                mma_bf16(acc[0][2 * p + 1], ah[0][0], ah[0][1], ah[0][2], ah[0][3], bl2, bl3);
                mma_bf16(acc[1][2 * p],     ah[1][0], ah[1][1], ah[1][2], ah[1][3], bl0, bl1);
                mma_bf16(acc[1][2 * p + 1], ah[1][0], ah[1][1], ah[1][2], ah[1][3], bl2, bl3);
                mma_bf16(acc[0][2 * p],     al[0][0], al[0][1], al[0][2], al[0][3], bh0, bh1);
                mma_bf16(acc[0][2 * p + 1], al[0][0], al[0][1], al[0][2], al[0][3], bh2, bh3);
                mma_bf16(acc[1][2 * p],     al[1][0], al[1][1], al[1][2], al[1][3], bh0, bh1);
                mma_bf16(acc[1][2 * p + 1], al[1][0], al[1][1], al[1][2], al[1][3], bh2, bh3);
            }
        }
        __syncthreads();
    }

    // ---- epilogue ----
    bool fuse = (fu != nullptr);
    bool dostats = (gsum != nullptr);
    float cs[NF][2], css[NF][2];
    #pragma unroll
    for (int nf = 0; nf < NF; nf++) { cs[nf][0] = cs[nf][1] = css[nf][0] = css[nf][1] = 0.f; }

    #pragma unroll
    for (int mt = 0; mt < 2; mt++) {
        int r0 = m0 + wm * 32 + mt * 16 + g;
        int r1 = r0 + 8;
        int re0 = 0, ce0 = 0, re1 = 0, ce1 = 0;
        if (fuse) {
            if (r0 < M) { re0 = __ldg(&erow[r0]); ce0 = __ldg(&ecol[r0]); }
            if (r1 < M) { re1 = __ldg(&erow[r1]); ce1 = __ldg(&ecol[r1]); }
        }
        #pragma unroll
        for (int nf = 0; nf < NF; nf++) {
            int c = nb0 + wn * 32 + nf * 8 + 2 * t4;
            if (r0 < M) {
                float x0 = acc[mt][nf][0], x1 = acc[mt][nf][1];
                if (fuse) {
                    float2 a = *(const float2*)(fu + (size_t)re0 * 64 + c);
                    float2 b = *(const float2*)(fv + (size_t)ce0 * 64 + c);
                    x0 += a.x + b.x; x1 += a.y + b.y;
                }
                *(float2*)(C + (size_t)r0 * ldc + c) = make_float2(x0, x1);
                cs[nf][0] += x0; css[nf][0] += x0 * x0;
                cs[nf][1] += x1; css[nf][1] += x1 * x1;
            }
            if (r1 < M) {
                float x0 = acc[mt][nf][2], x1 = acc[mt][nf][3];
                if (fuse) {
                    float2 a = *(const float2*)(fu + (size_t)re1 * 64 + c);
                    float2 b = *(const float2*)(fv + (size_t)ce1 * 64 + c);
                    x0 += a.x + b.x; x1 += a.y + b.y;
                }
                *(float2*)(C + (size_t)r1 * ldc + c) = make_float2(x0, x1);
                cs[nf][0] += x0; css[nf][0] += x0 * x0;
                cs[nf][1] += x1; css[nf][1] += x1 * x1;
            }
        }
    }
    if (dostats) {
        int cb = (nb0 % ldc) + wn * 32;
        #pragma unroll
        for (int nf = 0; nf < NF; nf++) {
            #pragma unroll
            for (int j = 0; j < 2; j++) {
                float s = cs[nf][j], q = css[nf][j];
                s += __shfl_down_sync(0xffffffffu, s, 16);
                q += __shfl_down_sync(0xffffffffu, q, 16);
                s += __shfl_down_sync(0xffffffffu, s, 8);
                q += __shfl_down_sync(0xffffffffu, q, 8);
                s += __shfl_down_sync(0xffffffffu, s, 4);
                q += __shfl_down_sync(0xffffffffu, q, 4);
                if (g == 0) {
                    int c = cb + nf * 8 + 2 * t4 + j;
                    atomicAdd(&gsum[c], s);
                    atomicAdd(&gssq[c], q);
                }
            }
        }
    }
}

// ---------------- BN finalize ----------------
__global__ void bnfin_all(const float* __restrict__ g_u, const float* __restrict__ be_u,
                          const float* __restrict__ g_v, const float* __restrict__ be_v,
                          const float* __restrict__ g_e, const float* __restrict__ be_e) {
    float* st = SF(OFF_STAT);
    int b = blockIdx.x, c = threadIdx.x;
    const float *sum, *ssq, *g, *be;
    float *scale, *shift;
    float invM;
    int C;
    if (b == 0) { sum = st; ssq = st + 256; g = g_u; be = be_u; scale = st + 1152; shift = st + 1408; invM = 1.f / NU; C = 256; }
    else if (b == 1) { sum = st + 512; ssq = st + 768; g = g_v; be = be_v; scale = st + 1664; shift = st + 1920; invM = 1.f / NV; C = 256; }
    else { sum = st + 1024; ssq = st + 1088; g = g_e; be = be_e; scale = st + 2176; shift = st + 2240; invM = 1.f / NE; C = 64; }
    if (c >= C) return;
    float mu = sum[c] * invM;
    float var = ssq[c] * invM - mu * mu;
    float sc = g[c] * rsqrtf(var + BN_EPS);
    scale[c] = sc;
    shift[c] = be[c] - mu * sc;
}

// ---------------- BN apply ----------------
__global__ void bnapply_all(float* __restrict__ out_u, float* __restrict__ out_v,
                            float* __restrict__ out_e) {
    float* st = SF(OFF_STAT);
    const size_t V1 = (size_t)NU * 64;
    const size_t V2 = V1 + (size_t)NV * 64;
    const size_t V3 = V2 + (size_t)NE * 16;
    size_t stride = (size_t)gridDim.x * blockDim.x;
    for (size_t v = blockIdx.x * (size_t)blockDim.x + threadIdx.x; v < V3; v += stride) {
        float4* p;
        const float* scale;
        const float* shift;
        int c4;
        if (v < V1)      { p = (float4*)out_u + v;        scale = st + 1152; shift = st + 1408; c4 = (int)((v & 63) << 2); }
        else if (v < V2) { p = (float4*)out_v + (v - V1); scale = st + 1664; shift = st + 1920; c4 = (int)(((v - V1) & 63) << 2); }
        else             { p = (float4*)out_e + (v - V2); scale = st + 2176; shift = st + 2240; c4 = (int)(((v - V2) & 15) << 2); }
        float4 x = *p;
        x.x = x.x * scale[c4 + 0] + shift[c4 + 0];
        x.y = x.y * scale[c4 + 1] + shift[c4 + 1];
        x.z = x.z * scale[c4 + 2] + shift[c4 + 2];
        x.w = x.w * scale[c4 + 3] + shift[c4 + 3];
        *p = x;
    }
}

// ---------------- launch ----------------
extern "C" void kernel_launch(void* const* d_in, const int* in_sizes, int n_in,
                              void* d_out, int out_size) {
    const float* xus     = (const float*)d_in[0];
    const float* xut     = (const float*)d_in[1];
    const float* xvs     = (const float*)d_in[2];
    const float* xvt     = (const float*)d_in[3];
    const float* xe_e    = (const float*)d_in[4];
    const float* xe_v2u  = (const float*)d_in[5];
    const float* xe_u2v  = (const float*)d_in[6];
    const int*   row_v2u = (const int*)d_in[7];
    const int*   col_v2u = (const int*)d_in[8];
    const int*   row_u2v = (const int*)d_in[9];
    const int*   col_u2v = (const int*)d_in[10];
    const int*   row_e   = (const int*)d_in[11];
    const int*   col_e   = (const int*)d_in[12];
    const float* attn_v2u = (const float*)d_in[13];
    const float* W_v2u    = (const float*)d_in[14];
    const float* g_v2u    = (const float*)d_in[16];
    const float* be_v2u   = (const float*)d_in[17];
    const float* attn_u2v = (const float*)d_in[18];
    const float* W_u2v    = (const float*)d_in[19];
    const float* g_u2v    = (const float*)d_in[21];
    const float* be_u2v   = (const float*)d_in[22];
    const float* W_e      = (const float*)d_in[23];
    const float* g_e      = (const float*)d_in[25];
    const float* be_e     = (const float*)d_in[26];

    float* out_u = (float*)d_out;
    float* out_v = out_u + (size_t)NU * 256;
    float* out_e = out_v + (size_t)NV * 256;

    unsigned char* base = nullptr;
    cudaGetSymbolAddress((void**)&base, g_scratch);
    bf* AHU = (bf*)(base + OFF_AHU); bf* ALU = (bf*)(base + OFF_ALU);
    bf* AHV = (bf*)(base + OFF_AHV); bf* ALV = (bf*)(base + OFF_ALV);
    bf* XEH = (bf*)(base + OFF_XEH); bf* XEL = (bf*)(base + OFF_XEL);
    bf* XUTH = (bf*)(base + OFF_XUTH); bf* XUTL = (bf*)(base + OFF_XUTL);
    bf* XVTH = (bf*)(base + OFF_XVTH); bf* XVTL = (bf*)(base + OFF_XVTL);
    bf* WTUH = (bf*)(base + OFF_WTUH); bf* WTUL = (bf*)(base + OFF_WTUL);
    bf* WTVH = (bf*)(base + OFF_WTVH); bf* WTVL = (bf*)(base + OFF_WTVL);
    bf* WTEH = (bf*)(base + OFF_WTEH); bf* WTEL = (bf*)(base + OFF_WTEL);
    float* pu = (float*)(base + OFF_PU);
    float* pv = (float*)(base + OFF_PV);
    float* wu = (float*)(base + OFF_WU);
    float* wv = (float*)(base + OFF_WV);
    int* off_u = (int*)(base + OFF_OFFU);
    int* off_v = (int*)(base + OFF_OFFV);
    int* eid_u = (int*)(base + OFF_EIDU);
    int* eid_v = (int*)(base + OFF_EIDV);
    float* st = (float*)(base + OFF_STAT);
    float* sum_u = st + 0,    *ssq_u = st + 256;
    float* sum_v = st + 512,  *ssq_v = st + 768;
    float* sum_e = st + 1024, *ssq_e = st + 1088;

    static constexpr int SMEM_G = 2 * GSTAGE; // 49152
    cudaFuncSetAttribute(gemm_bf3, cudaFuncAttributeMaxDynamicSharedMemorySize, SMEM_G);

    // prep (independent work first)
    tsplit_k<<<128, 256>>>(W_e, 576, 64, WTEH, WTEL);
    split_k<<<2048, 256>>>(xut, XUTH, XUTL, (size_t)NU * 256);
    split_k<<<2048, 256>>>(xvt, XVTH, XVTL, (size_t)NV * 256);

    // projection GEMMs, merged (z = u/v)
    gemm_bf3<<<dim3(157, 1, 2), 256, SMEM_G>>>(
        XUTH, XUTL, WTEH + 64, WTEL + 64, pu,
        XVTH, XVTL, WTEH + 320, WTEL + 320, pv,
        256, 576, 64, NU, 256,
        nullptr, nullptr, nullptr, nullptr,
        nullptr, nullptr, nullptr, nullptr);

    init_k<<<(NU + 255) / 256, 256>>>();
    logits_k<<<(NU + NV) / 8, 256>>>(xus, xvs, attn_u2v, attn_v2u);
    softmax_reduce_k<<<2, 1024>>>();
    weights_k<<<(NU + 255) / 256, 256>>>();
    hist_k<<<(2 * NE + 255) / 256, 256>>>(row_v2u, col_u2v);
    scan_k<<<2, 1024>>>();
    scatter_k<<<(2 * NE + 255) / 256, 256>>>(row_v2u, col_u2v);

    split_k<<<4096, 256>>>(xe_e, XEH, XEL, (size_t)NE * 64);
    tsplit_k<<<512, 256>>>(W_v2u, DK, 256, WTUH, WTUL);
    tsplit_k<<<512, 256>>>(W_u2v, DK, 256, WTVH, WTVL);

    // aggregation, both directions in one launch
    agg_k<<<2 * NU, 256>>>(
        off_u, eid_u, col_v2u, wv, xvs, xe_v2u, xut, AHU, ALU,
        off_v, eid_v, row_u2v, wu, xus, xe_u2v, xvt, AHV, ALV);

    // node GEMMs, merged (z = u/v, y = 4 n-blocks of 64), fused BN stats
    gemm_bf3<<<dim3(157, 4, 2), 256, SMEM_G>>>(
        AHU, ALU, WTUH, WTUL, out_u,
        AHV, ALV, WTVH, WTVL, out_v,
        DK, DK, 256, NU, DK,
        nullptr, nullptr, nullptr, nullptr,
        sum_u, ssq_u, sum_v, ssq_v);
    // edge GEMM + fused combine + fused BN stats
    gemm_bf3<<<dim3(NE / 128, 1, 1), 256, SMEM_G>>>(
        XEH, XEL, WTEH, WTEL, out_e,
        XEH, XEL, WTEH, WTEL, out_e,
        64, 576, 64, NE, 64,
        pu, pv, row_e, col_e,
        sum_e, ssq_e, sum_e, ssq_e);

    // BN finalize + single fused apply pass
    bnfin_all<<<3, 256>>>(g_v2u, be_v2u, g_u2v, be_u2v, g_e, be_e);
    bnapply_all<<<4096, 256>>>(out_u, out_v, out_e);
}

// round 17
// speedup vs baseline: 1.1154x; 1.1154x over previous
#include <cuda_runtime.h>
#include <cuda_bf16.h>
#include <cstdint>
#include <cstddef>

// ---------------- problem constants ----------------
#define NU 20000
#define NV 20000
#define NE 320000
#define BN_EPS 1e-5f
#define NEG_BIG (-3.402823466e+38f)
#define DK 896

typedef __nv_bfloat16 bf;

// ---------------- scratch arena ----------------
static constexpr size_t AL(size_t x) { return (x + 255) & ~(size_t)255; }
static constexpr size_t SZ_AH   = AL((size_t)NU * DK * 2);
static constexpr size_t SZ_XE   = AL((size_t)NE * 64 * 2);
static constexpr size_t SZ_XT   = AL((size_t)NU * 256 * 2);
static constexpr size_t SZ_WTU  = AL((size_t)256 * DK * 2);
static constexpr size_t SZ_WTE  = AL((size_t)64 * 576 * 2);
static constexpr size_t SZ_P    = AL((size_t)NU * 64 * 4);
static constexpr size_t SZ_L    = AL((size_t)NU * 4);
static constexpr size_t SZ_OFF  = AL((size_t)(NU + 1) * 4);
static constexpr size_t SZ_EID  = AL((size_t)NE * 4);
static constexpr size_t SZ_RED  = 256;
static constexpr size_t SZ_STAT = 16384;

static constexpr size_t OFF_AHU  = 0;
static constexpr size_t OFF_ALU  = OFF_AHU + SZ_AH;
static constexpr size_t OFF_AHV  = OFF_ALU + SZ_AH;
static constexpr size_t OFF_ALV  = OFF_AHV + SZ_AH;
static constexpr size_t OFF_XEH  = OFF_ALV + SZ_AH;
static constexpr size_t OFF_XEL  = OFF_XEH + SZ_XE;
static constexpr size_t OFF_XUTH = OFF_XEL + SZ_XE;
static constexpr size_t OFF_XUTL = OFF_XUTH + SZ_XT;
static constexpr size_t OFF_XVTH = OFF_XUTL + SZ_XT;
static constexpr size_t OFF_XVTL = OFF_XVTH + SZ_XT;
static constexpr size_t OFF_WTUH = OFF_XVTL + SZ_XT;
static constexpr size_t OFF_WTUL = OFF_WTUH + SZ_WTU;
static constexpr size_t OFF_WTVH = OFF_WTUL + SZ_WTU;
static constexpr size_t OFF_WTVL = OFF_WTVH + SZ_WTU;
static constexpr size_t OFF_WTEH = OFF_WTVL + SZ_WTU;
static constexpr size_t OFF_WTEL = OFF_WTEH + SZ_WTE;
static constexpr size_t OFF_PU   = OFF_WTEL + SZ_WTE;
static constexpr size_t OFF_PV   = OFF_PU + SZ_P;
static constexpr size_t OFF_LU   = OFF_PV + SZ_P;
static constexpr size_t OFF_LV   = OFF_LU + SZ_L;
static constexpr size_t OFF_WU   = OFF_LV + SZ_L;
static constexpr size_t OFF_WV   = OFF_WU + SZ_L;
static constexpr size_t OFF_CNTU = OFF_WV + SZ_L;
static constexpr size_t OFF_CNTV = OFF_CNTU + SZ_L;
static constexpr size_t OFF_OFFU = OFF_CNTV + SZ_L;
static constexpr size_t OFF_OFFV = OFF_OFFU + SZ_OFF;
static constexpr size_t OFF_CURU = OFF_OFFV + SZ_OFF;
static constexpr size_t OFF_CURV = OFF_CURU + SZ_L;
static constexpr size_t OFF_EIDU = OFF_CURV + SZ_L;
static constexpr size_t OFF_EIDV = OFF_EIDU + SZ_EID;
static constexpr size_t OFF_RED  = OFF_EIDV + SZ_EID;
static constexpr size_t OFF_STAT = OFF_RED + SZ_RED;
static constexpr size_t SCRATCH_TOTAL = OFF_STAT + SZ_STAT;

__device__ __align__(1024) unsigned char g_scratch[SCRATCH_TOTAL];

__device__ __forceinline__ float* SF(size_t off) { return (float*)(g_scratch + off); }
__device__ __forceinline__ int*   SI(size_t off) { return (int*)(g_scratch + off); }

// ---------------- helpers ----------------
__device__ __forceinline__ uint32_t s2u(const void* p) {
    uint32_t a;
    asm("{ .reg .u64 t; cvta.to.shared.u64 t, %1; cvt.u32.u64 %0, t; }" : "=r"(a) : "l"(p));
    return a;
}
__device__ __forceinline__ void cpa16(uint32_t dst, const void* src, int srcsz) {
    asm volatile("cp.async.cg.shared.global [%0], [%1], 16, %2;"
        :: "r"(dst), "l"(src), "r"(srcsz) : "memory");
}
#define CP_COMMIT() asm volatile("cp.async.commit_group;" ::: "memory")
#define CP_WAIT1()  asm volatile("cp.async.wait_group 1;" ::: "memory")
#define CP_WAIT0()  asm volatile("cp.async.wait_group 0;" ::: "memory")

__device__ __forceinline__ void ldsm4(uint32_t& r0, uint32_t& r1, uint32_t& r2, uint32_t& r3,
                                      uint32_t addr) {
    asm volatile("ldmatrix.sync.aligned.m8n8.x4.shared.b16 {%0,%1,%2,%3}, [%4];"
        : "=r"(r0), "=r"(r1), "=r"(r2), "=r"(r3) : "r"(addr));
}
__device__ __forceinline__ void mma_bf16(float* c,
        uint32_t a0, uint32_t a1, uint32_t a2, uint32_t a3, uint32_t b0, uint32_t b1) {
    asm volatile("mma.sync.aligned.m16n8k16.row.col.f32.bf16.bf16.f32 "
        "{%0,%1,%2,%3}, {%4,%5,%6,%7}, {%8,%9}, {%0,%1,%2,%3};"
        : "+f"(c[0]), "+f"(c[1]), "+f"(c[2]), "+f"(c[3])
        : "r"(a0), "r"(a1), "r"(a2), "r"(a3), "r"(b0), "r"(b1));
}
__device__ __forceinline__ void bsplit(float v, bf& h, bf& l) {
    h = __float2bfloat16(v);
    l = __float2bfloat16(v - __bfloat162float(h));
}
__device__ __forceinline__ uint32_t swz(uint32_t row, uint32_t seg) {
    return (row << 6) | (((seg ^ (row >> 1)) & 3u) << 4);
}

// ---------------- init ----------------
__global__ void init_k() {
    int i = blockIdx.x * blockDim.x + threadIdx.x;
    if (i < NU) { SI(OFF_CNTU)[i] = 0; SI(OFF_CNTV)[i] = 0; }
    if (i < 1152) SF(OFF_STAT)[i] = 0.f;
}

// ---------------- attention ----------------
__global__ void logits_k(const float* __restrict__ xus, const float* __restrict__ xvs,
                         const float* __restrict__ attn_u2v, const float* __restrict__ attn_v2u) {
    int w = (blockIdx.x * blockDim.x + threadIdx.x) >> 5;
    int lane = threadIdx.x & 31;
    if (w >= NU + NV) return;
    const float* x; const float* a; float* out; int r;
    if (w < NU) { x = xus; a = attn_u2v; out = SF(OFF_LU); r = w; }
    else        { x = xvs; a = attn_v2u; out = SF(OFF_LV); r = w - NU; }
    float s = 0.f;
    const float* xr = x + (size_t)r * 256;
    #pragma unroll
    for (int k = lane; k < 256; k += 32) s += xr[k] * a[k];
    #pragma unroll
    for (int o = 16; o; o >>= 1) s += __shfl_down_sync(0xffffffffu, s, o);
    if (lane == 0) out[r] = s;
}

__global__ void softmax_reduce_k() {
    const float* l = blockIdx.x ? SF(OFF_LV) : SF(OFF_LU);
    __shared__ float sh[1024];
    int t = threadIdx.x;
    float m = NEG_BIG;
    for (int i = t; i < NU; i += 1024) m = fmaxf(m, l[i]);
    sh[t] = m; __syncthreads();
    for (int s = 512; s; s >>= 1) { if (t < s) sh[t] = fmaxf(sh[t], sh[t + s]); __syncthreads(); }
    float mx = sh[0]; __syncthreads();
    float su = 0.f;
    for (int i = t; i < NU; i += 1024) su += expf(l[i] - mx);
    sh[t] = su; __syncthreads();
    for (int s = 512; s; s >>= 1) { if (t < s) sh[t] += sh[t + s]; __syncthreads(); }
    if (t == 0) { float* red = SF(OFF_RED); red[blockIdx.x * 2] = mx; red[blockIdx.x * 2 + 1] = sh[0]; }
}

__global__ void weights_k() {
    int i = blockIdx.x * blockDim.x + threadIdx.x;
    if (i >= NU) return;
    float* red = SF(OFF_RED);
    SF(OFF_WU)[i] = expf(SF(OFF_LU)[i] - red[0]) / red[1];
    SF(OFF_WV)[i] = expf(SF(OFF_LV)[i] - red[2]) / red[3];
}

// ---------------- CSR build ----------------
__global__ void hist_k(const int* __restrict__ row_v2u, const int* __restrict__ col_u2v) {
    int i = blockIdx.x * blockDim.x + threadIdx.x;
    if (i < NE) atomicAdd(&SI(OFF_CNTU)[row_v2u[i]], 1);
    else if (i < 2 * NE) atomicAdd(&SI(OFF_CNTV)[col_u2v[i - NE]], 1);
}

// single-pass shfl-based exclusive scan; 2 blocks (U, V), 1024 threads.
// thread t serially scans its 20-element chunk; one warp-shuffle block scan.
#define SCAN_CH 20
__global__ void scan_k() {
    const int* cnt = blockIdx.x ? SI(OFF_CNTV) : SI(OFF_CNTU);
    int* off = blockIdx.x ? SI(OFF_OFFV) : SI(OFF_OFFU);
    int* cur = blockIdx.x ? SI(OFF_CURV) : SI(OFF_CURU);
    __shared__ int wsum[32];
    int t = threadIdx.x;
    int lane = t & 31, wid = t >> 5;
    int base = t * SCAN_CH;

    int local[SCAN_CH];
    int sum = 0;
    #pragma unroll
    for (int i = 0; i < SCAN_CH; i++) {
        int idx = base + i;
        int v = (idx < NU) ? cnt[idx] : 0;
        local[i] = sum;          // exclusive within chunk
        sum += v;
    }
    // inclusive warp scan of chunk sums
    int inc = sum;
    #pragma unroll
    for (int o = 1; o < 32; o <<= 1) {
        int n = __shfl_up_sync(0xffffffffu, inc, o);
        if (lane >= o) inc += n;
    }
    if (lane == 31) wsum[wid] = inc;
    __syncthreads();
    if (wid == 0) {
        int v = wsum[lane];
        #pragma unroll
        for (int o = 1; o < 32; o <<= 1) {
            int n = __shfl_up_sync(0xffffffffu, v, o);
            if (lane >= o) v += n;
        }
        wsum[lane] = v;          // inclusive warp prefix
    }
    __syncthreads();
    int wbase = (wid > 0) ? wsum[wid - 1] : 0;
    int excl = wbase + inc - sum;    // exclusive prefix for this thread's chunk
    #pragma unroll
    for (int i = 0; i < SCAN_CH; i++) {
        int idx = base + i;
        if (idx < NU) { int o = excl + local[i]; off[idx] = o; cur[idx] = o; }
    }
    if (t == 1023) off[NU] = excl + sum;
}

__global__ void scatter_k(const int* __restrict__ row_v2u, const int* __restrict__ col_u2v) {
    int i = blockIdx.x * blockDim.x + threadIdx.x;
    if (i < NE) {
        int p = atomicAdd(&SI(OFF_CURU)[row_v2u[i]], 1);
        SI(OFF_EIDU)[p] = i;
    } else if (i < 2 * NE) {
        int e = i - NE;
        int p = atomicAdd(&SI(OFF_CURV)[col_u2v[e]], 1);
        SI(OFF_EIDV)[p] = e;
    }
}

// ---------------- bf16 splits ----------------
__global__ void split_k(const float* __restrict__ x, bf* __restrict__ hi,
                        bf* __restrict__ lo, size_t n) {
    size_t stride = (size_t)gridDim.x * blockDim.x;
    for (size_t i = blockIdx.x * (size_t)blockDim.x + threadIdx.x; i < n; i += stride) {
        bf h, l;
        bsplit(x[i], h, l);
        hi[i] = h; lo[i] = l;
    }
}

__global__ void tsplit_k(const float* __restrict__ W, int K, int N,
                         bf* __restrict__ hi, bf* __restrict__ lo) {
    int total = K * N;
    int stride = gridDim.x * blockDim.x;
    for (int i = blockIdx.x * blockDim.x + threadIdx.x; i < total; i += stride) {
        int nn = i / K, kk = i - nn * K;
        bf h, l;
        bsplit(W[(size_t)kk * N + nn], h, l);
        hi[i] = h; lo[i] = l;
    }
}

// ---------------- aggregation (R15/R12 scalar unroll-4, merged u/v) ----------------
#define AGG_BT 128
__global__ __launch_bounds__(256) void agg_k(
        const int* __restrict__ off0, const int* __restrict__ eids0,
        const int* __restrict__ soe0, const float* __restrict__ w0,
        const float* __restrict__ xs0, const float* __restrict__ xe0,
        const float* __restrict__ xt0, bf* __restrict__ hh0, bf* __restrict__ hl0,
        const int* __restrict__ off1, const int* __restrict__ eids1,
        const int* __restrict__ soe1, const float* __restrict__ w1,
        const float* __restrict__ xs1, const float* __restrict__ xe1,
        const float* __restrict__ xt1, bf* __restrict__ hh1, bf* __restrict__ hl1) {
    __shared__ int   s_src[AGG_BT];
    __shared__ float s_w[AGG_BT];
    __shared__ int   s_eid[AGG_BT];
    int u = blockIdx.x;
    bool second = (u >= NU);
    if (second) u -= NU;
    const int* off = second ? off1 : off0;
    const int* eids = second ? eids1 : eids0;
    const int* soe = second ? soe1 : soe0;
    const float* w = second ? w1 : w0;
    const float* xsrc = second ? xs1 : xs0;
    const float* xe = second ? xe1 : xe0;
    const float* xtgt = second ? xt1 : xt0;
    bf* hhi = second ? hh1 : hh0;
    bf* hlo = second ? hl1 : hl0;

    int t = threadIdx.x;
    int s = off[u], e = off[u + 1];
    int deg = e - s;
    float sum = 0.f, mx = NEG_BIG, esum = 0.f, emx = NEG_BIG;
    for (int base = s; base < e; base += AGG_BT) {
        int cnt = min(AGG_BT, e - base);
        __syncthreads();
        if (t < cnt) {
            int eid = __ldg(&eids[base + t]);
            s_eid[t] = eid;
            int sc = __ldg(&soe[eid]);
            s_src[t] = sc;
            s_w[t] = __ldg(&w[sc]);
        }
        __syncthreads();
        #pragma unroll 4
        for (int j = 0; j < cnt; j++) {
            float v = s_w[j] * __ldg(&xsrc[(size_t)s_src[j] * 256 + t]);
            sum += v;
            mx = fmaxf(mx, v);
        }
        if (t < 64) {
            #pragma unroll 4
            for (int j = 0; j < cnt; j++) {
                float ev = __ldg(&xe[(size_t)s_eid[j] * 64 + t]);
                esum += ev;
                emx = fmaxf(emx, ev);
            }
        }
    }
    float inv = 1.f / (float)(deg > 0 ? deg : 1);
    size_t base = (size_t)u * DK;
    bf h, l;
    bsplit(__ldg(&xtgt[(size_t)u * 256 + t]), h, l); hhi[base + t] = h;       hlo[base + t] = l;
    bsplit(sum * inv, h, l);                         hhi[base + 256 + t] = h; hlo[base + 256 + t] = l;
    bsplit((deg > 0) ? mx : 0.f, h, l);              hhi[base + 512 + t] = h; hlo[base + 512 + t] = l;
    if (t < 64) {
        bsplit(esum * inv, h, l);                    hhi[base + 768 + t] = h; hlo[base + 768 + t] = l;
        bsplit((deg > 0) ? emx : 0.f, h, l);         hhi[base + 832 + t] = h; hlo[base + 832 + t] = l;
    }
}

// ---------------- bf16 3-pass mma GEMM (2-stage, 3 CTAs/SM — best measured) ----------------
#define GROWS 384
#define GSTAGE (GROWS * 64)
__global__ __launch_bounds__(256, 3) void gemm_bf3(
        const bf* __restrict__ Ah0, const bf* __restrict__ Al0,
        const bf* __restrict__ Bh0, const bf* __restrict__ Bl0, float* __restrict__ C0,
        const bf* __restrict__ Ah1, const bf* __restrict__ Al1,
        const bf* __restrict__ Bh1, const bf* __restrict__ Bl1, float* __restrict__ C1,
        int lda, int ldb, int ldc, int M, int Kt,
        const float* __restrict__ fu, const float* __restrict__ fv,
        const int* __restrict__ erow, const int* __restrict__ ecol,
        float* __restrict__ gsum0, float* __restrict__ gssq0,
        float* __restrict__ gsum1, float* __restrict__ gssq1) {
    extern __shared__ unsigned char smemraw[];
    constexpr int NF = 4;
    constexpr int NITER = (GROWS * 4) / 256;

    int sel = blockIdx.z;
    const bf* Ah = sel ? Ah1 : Ah0;
    const bf* Al = sel ? Al1 : Al0;
    const bf* Bh = sel ? Bh1 : Bh0;
    const bf* Bl = sel ? Bl1 : Bl0;
    float* C = sel ? C1 : C0;
    float* gsum = sel ? gsum1 : gsum0;
    float* gssq = sel ? gssq1 : gssq0;

    int tid = threadIdx.x;
    int lane = tid & 31, warp = tid >> 5;
    int wm = warp >> 1, wn = warp & 1;
    int m0 = blockIdx.x * 128;
    int nb0 = blockIdx.y * 64;
    int g = lane >> 2, t4 = lane & 3;
    uint32_t sbase = s2u(smemraw);

    float acc[2][NF][4];
    #pragma unroll
    for (int a = 0; a < 2; a++)
        #pragma unroll
        for (int b = 0; b < NF; b++)
            #pragma unroll
            for (int q = 0; q < 4; q++) acc[a][b][q] = 0.f;

    int nch = Kt >> 5;

    uint32_t a_row = (uint32_t)(wm * 32 + (lane & 15));
    uint32_t a_sg  = (uint32_t)(lane >> 4);
    uint32_t b_row = (uint32_t)(256 + wn * 32 + (lane & 7) + ((lane >> 4) << 3));
    uint32_t b_sg  = (uint32_t)((lane >> 3) & 1);

    auto issue = [&](int c) {
        uint32_t stg = sbase + (uint32_t)(c & 1) * GSTAGE;
        int kel = c * 32;
        #pragma unroll
        for (int i = 0; i < NITER; i++) {
            int task = tid + 256 * i;
            uint32_t row = (uint32_t)(task >> 2);
            uint32_t seg = (uint32_t)(task & 3);
            const bf* src;
            int sz = 16;
            if (row < 256) {
                int r = row & 127;
                int gr = m0 + r;
                const bf* Abase = (row < 128) ? Ah : Al;
                if (gr >= M) { gr = M - 1; sz = 0; }
                src = Abase + (size_t)gr * lda + kel + seg * 8;
            } else {
                uint32_t r2 = row - 256;
                int rb = r2 & 63;
                const bf* Bbase = (r2 < 64) ? Bh : Bl;
                src = Bbase + (size_t)(nb0 + rb) * ldb + kel + seg * 8;
            }
            cpa16(stg + swz(row, seg), src, sz);
        }
        CP_COMMIT();
    };

    issue(0);
    for (int c = 0; c < nch; c++) {
        if (c + 1 < nch) { issue(c + 1); CP_WAIT1(); }
        else             { CP_WAIT0(); }
        __syncthreads();
        uint32_t stg = sbase + (uint32_t)(c & 1) * GSTAGE;
        #pragma unroll
        for (int ks = 0; ks < 2; ks++) {
            uint32_t ah[2][4], al[2][4];
            #pragma unroll
            for (int mt = 0; mt < 2; mt++) {
                uint32_t row = a_row + (uint32_t)(mt * 16);
                uint32_t ad = stg + swz(row, a_sg + 2u * (uint32_t)ks);
                ldsm4(ah[mt][0], ah[mt][1], ah[mt][2], ah[mt][3], ad);
                ldsm4(al[mt][0], al[mt][1], al[mt][2], al[mt][3], ad + 8192u);
            }
            #pragma unroll
            for (int p = 0; p < 2; p++) {
                uint32_t row = b_row + (uint32_t)(p * 16);
                uint32_t bd = stg + swz(row, b_sg + 2u * (uint32_t)ks);
                uint32_t bh0, bh1, bh2, bh3, bl0, bl1, bl2, bl3;
                ldsm4(bh0, bh1, bh2, bh3, bd);
                ldsm4(bl0, bl1, bl2, bl3, bd + 4096u);
                mma_bf16(acc[0][2 * p],     ah[0][0], ah[0][1], ah[0][2], ah[0][3], bh0, bh1);
                mma_bf16(acc[0][2 * p + 1], ah[0][0], ah[0][1], ah[0][2], ah[0][3], bh2, bh3);
                mma_bf16(acc[1][2 * p],     ah[1][0], ah[1][1], ah[1][2], ah[1][3], bh0, bh1);
                mma_bf16(acc[1][2 * p + 1], ah[1][0], ah[1][1], ah[1][2], ah[1][3], bh2, bh3);
                mma_bf16(acc[0][2 * p],     ah[0][0], ah[0][1], ah[0][2], ah[0][3], bl0, bl1);
                mma_bf16(acc[0][2 * p + 1], ah[0][0], ah[0][1], ah[0][2], ah[0][3], bl2, bl3);
                mma_bf16(acc[1][2 * p],     ah[1][0], ah[1][1], ah[1][2], ah[1][3], bl0, bl1);
                mma_bf16(acc[1][2 * p + 1], ah[1][0], ah[1][1], ah[1][2], ah[1][3], bl2, bl3);
                mma_bf16(acc[0][2 * p],     al[0][0], al[0][1], al[0][2], al[0][3], bh0, bh1);
                mma_bf16(acc[0][2 * p + 1], al[0][0], al[0][1], al[0][2], al[0][3], bh2, bh3);
                mma_bf16(acc[1][2 * p],     al[1][0], al[1][1], al[1][2], al[1][3], bh0, bh1);
                mma_bf16(acc[1][2 * p + 1], al[1][0], al[1][1], al[1][2], al[1][3], bh2, bh3);
            }
        }
        __syncthreads();
    }

    // ---- epilogue ----
    bool fuse = (fu != nullptr);
    bool dostats = (gsum != nullptr);
    float cs[NF][2], css[NF][2];
    #pragma unroll
    for (int nf = 0; nf < NF; nf++) { cs[nf][0] = cs[nf][1] = css[nf][0] = css[nf][1] = 0.f; }

    #pragma unroll
    for (int mt = 0; mt < 2; mt++) {
        int r0 = m0 + wm * 32 + mt * 16 + g;
        int r1 = r0 + 8;
        int re0 = 0, ce0 = 0, re1 = 0, ce1 = 0;
        if (fuse) {
            if (r0 < M) { re0 = __ldg(&erow[r0]); ce0 = __ldg(&ecol[r0]); }
            if (r1 < M) { re1 = __ldg(&erow[r1]); ce1 = __ldg(&ecol[r1]); }
        }
        #pragma unroll
        for (int nf = 0; nf < NF; nf++) {
            int c = nb0 + wn * 32 + nf * 8 + 2 * t4;
            if (r0 < M) {
                float x0 = acc[mt][nf][0], x1 = acc[mt][nf][1];
                if (fuse) {
                    float2 a = *(const float2*)(fu + (size_t)re0 * 64 + c);
                    float2 b = *(const float2*)(fv + (size_t)ce0 * 64 + c);
                    x0 += a.x + b.x; x1 += a.y + b.y;
                }
                *(float2*)(C + (size_t)r0 * ldc + c) = make_float2(x0, x1);
                cs[nf][0] += x0; css[nf][0] += x0 * x0;
                cs[nf][1] += x1; css[nf][1] += x1 * x1;
            }
            if (r1 < M) {
                float x0 = acc[mt][nf][2], x1 = acc[mt][nf][3];
                if (fuse) {
                    float2 a = *(const float2*)(fu + (size_t)re1 * 64 + c);
                    float2 b = *(const float2*)(fv + (size_t)ce1 * 64 + c);
                    x0 += a.x + b.x; x1 += a.y + b.y;
                }
                *(float2*)(C + (size_t)r1 * ldc + c) = make_float2(x0, x1);
                cs[nf][0] += x0; css[nf][0] += x0 * x0;
                cs[nf][1] += x1; css[nf][1] += x1 * x1;
            }
        }
    }
    if (dostats) {
        int cb = (nb0 % ldc) + wn * 32;
        #pragma unroll
        for (int nf = 0; nf < NF; nf++) {
            #pragma unroll
            for (int j = 0; j < 2; j++) {
                float s = cs[nf][j], q = css[nf][j];
                s += __shfl_down_sync(0xffffffffu, s, 16);
                q += __shfl_down_sync(0xffffffffu, q, 16);
                s += __shfl_down_sync(0xffffffffu, s, 8);
                q += __shfl_down_sync(0xffffffffu, q, 8);
                s += __shfl_down_sync(0xffffffffu, s, 4);
                q += __shfl_down_sync(0xffffffffu, q, 4);
                if (g == 0) {
                    int c = cb + nf * 8 + 2 * t4 + j;
                    atomicAdd(&gsum[c], s);
                    atomicAdd(&gssq[c], q);
                }
            }
        }
    }
}

// ---------------- BN finalize ----------------
__global__ void bnfin_all(const float* __restrict__ g_u, const float* __restrict__ be_u,
                          const float* __restrict__ g_v, const float* __restrict__ be_v,
                          const float* __restrict__ g_e, const float* __restrict__ be_e) {
    float* st = SF(OFF_STAT);
    int b = blockIdx.x, c = threadIdx.x;
    const float *sum, *ssq, *g, *be;
    float *scale, *shift;
    float invM;
    int C;
    if (b == 0) { sum = st; ssq = st + 256; g = g_u; be = be_u; scale = st + 1152; shift = st + 1408; invM = 1.f / NU; C = 256; }
    else if (b == 1) { sum = st + 512; ssq = st + 768; g = g_v; be = be_v; scale = st + 1664; shift = st + 1920; invM = 1.f / NV; C = 256; }
    else { sum = st + 1024; ssq = st + 1088; g = g_e; be = be_e; scale = st + 2176; shift = st + 2240; invM = 1.f / NE; C = 64; }
    if (c >= C) return;
    float mu = sum[c] * invM;
    float var = ssq[c] * invM - mu * mu;
    float sc = g[c] * rsqrtf(var + BN_EPS);
    scale[c] = sc;
    shift[c] = be[c] - mu * sc;
}

// ---------------- BN apply ----------------
__global__ void bnapply_all(float* __restrict__ out_u, float* __restrict__ out_v,
                            float* __restrict__ out_e) {
    float* st = SF(OFF_STAT);
    const size_t V1 = (size_t)NU * 64;
    const size_t V2 = V1 + (size_t)NV * 64;
    const size_t V3 = V2 + (size_t)NE * 16;
    size_t stride = (size_t)gridDim.x * blockDim.x;
    for (size_t v = blockIdx.x * (size_t)blockDim.x + threadIdx.x; v < V3; v += stride) {
        float4* p;
        const float* scale;
        const float* shift;
        int c4;
        if (v < V1)      { p = (float4*)out_u + v;        scale = st + 1152; shift = st + 1408; c4 = (int)((v & 63) << 2); }
        else if (v < V2) { p = (float4*)out_v + (v - V1); scale = st + 1664; shift = st + 1920; c4 = (int)(((v - V1) & 63) << 2); }
        else             { p = (float4*)out_e + (v - V2); scale = st + 2176; shift = st + 2240; c4 = (int)(((v - V2) & 15) << 2); }
        float4 x = *p;
        x.x = x.x * scale[c4 + 0] + shift[c4 + 0];
        x.y = x.y * scale[c4 + 1] + shift[c4 + 1];
        x.z = x.z * scale[c4 + 2] + shift[c4 + 2];
        x.w = x.w * scale[c4 + 3] + shift[c4 + 3];
        *p = x;
    }
}

// ---------------- launch ----------------
extern "C" void kernel_launch(void* const* d_in, const int* in_sizes, int n_in,
                              void* d_out, int out_size) {
    const float* xus     = (const float*)d_in[0];
    const float* xut     = (const float*)d_in[1];
    const float* xvs     = (const float*)d_in[2];
    const float* xvt     = (const float*)d_in[3];
    const float* xe_e    = (const float*)d_in[4];
    const float* xe_v2u  = (const float*)d_in[5];
    const float* xe_u2v  = (const float*)d_in[6];
    const int*   row_v2u = (const int*)d_in[7];
    const int*   col_v2u = (const int*)d_in[8];
    const int*   row_u2v = (const int*)d_in[9];
    const int*   col_u2v = (const int*)d_in[10];
    const int*   row_e   = (const int*)d_in[11];
    const int*   col_e   = (const int*)d_in[12];
    const float* attn_v2u = (const float*)d_in[13];
    const float* W_v2u    = (const float*)d_in[14];
    const float* g_v2u    = (const float*)d_in[16];
    const float* be_v2u   = (const float*)d_in[17];
    const float* attn_u2v = (const float*)d_in[18];
    const float* W_u2v    = (const float*)d_in[19];
    const float* g_u2v    = (const float*)d_in[21];
    const float* be_u2v   = (const float*)d_in[22];
    const float* W_e      = (const float*)d_in[23];
    const float* g_e      = (const float*)d_in[25];
    const float* be_e     = (const float*)d_in[26];

    float* out_u = (float*)d_out;
    float* out_v = out_u + (size_t)NU * 256;
    float* out_e = out_v + (size_t)NV * 256;

    unsigned char* base = nullptr;
    cudaGetSymbolAddress((void**)&base, g_scratch);
    bf* AHU = (bf*)(base + OFF_AHU); bf* ALU = (bf*)(base + OFF_ALU);
    bf* AHV = (bf*)(base + OFF_AHV); bf* ALV = (bf*)(base + OFF_ALV);
    bf* XEH = (bf*)(base + OFF_XEH); bf* XEL = (bf*)(base + OFF_XEL);
    bf* XUTH = (bf*)(base + OFF_XUTH); bf* XUTL = (bf*)(base + OFF_XUTL);
    bf* XVTH = (bf*)(base + OFF_XVTH); bf* XVTL = (bf*)(base + OFF_XVTL);
    bf* WTUH = (bf*)(base + OFF_WTUH); bf* WTUL = (bf*)(base + OFF_WTUL);
    bf* WTVH = (bf*)(base + OFF_WTVH); bf* WTVL = (bf*)(base + OFF_WTVL);
    bf* WTEH = (bf*)(base + OFF_WTEH); bf* WTEL = (bf*)(base + OFF_WTEL);
    float* pu = (float*)(base + OFF_PU);
    float* pv = (float*)(base + OFF_PV);
    float* wu = (float*)(base + OFF_WU);
    float* wv = (float*)(base + OFF_WV);
    int* off_u = (int*)(base + OFF_OFFU);
    int* off_v = (int*)(base + OFF_OFFV);
    int* eid_u = (int*)(base + OFF_EIDU);
    int* eid_v = (int*)(base + OFF_EIDV);
    float* st = (float*)(base + OFF_STAT);
    float* sum_u = st + 0,    *ssq_u = st + 256;
    float* sum_v = st + 512,  *ssq_v = st + 768;
    float* sum_e = st + 1024, *ssq_e = st + 1088;

    static constexpr int SMEM_G = 2 * GSTAGE; // 49152
    cudaFuncSetAttribute(gemm_bf3, cudaFuncAttributeMaxDynamicSharedMemorySize, SMEM_G);

    // prep (independent work first)
    tsplit_k<<<128, 256>>>(W_e, 576, 64, WTEH, WTEL);
    split_k<<<2048, 256>>>(xut, XUTH, XUTL, (size_t)NU * 256);
    split_k<<<2048, 256>>>(xvt, XVTH, XVTL, (size_t)NV * 256);

    // projection GEMMs, merged (z = u/v)
    gemm_bf3<<<dim3(157, 1, 2), 256, SMEM_G>>>(
        XUTH, XUTL, WTEH + 64, WTEL + 64, pu,
        XVTH, XVTL, WTEH + 320, WTEL + 320, pv,
        256, 576, 64, NU, 256,
        nullptr, nullptr, nullptr, nullptr,
        nullptr, nullptr, nullptr, nullptr);

    init_k<<<(NU + 255) / 256, 256>>>();
    logits_k<<<(NU + NV) / 8, 256>>>(xus, xvs, attn_u2v, attn_v2u);
    softmax_reduce_k<<<2, 1024>>>();
    weights_k<<<(NU + 255) / 256, 256>>>();
    hist_k<<<(2 * NE + 255) / 256, 256>>>(row_v2u, col_u2v);
    scan_k<<<2, 1024>>>();
    scatter_k<<<(2 * NE + 255) / 256, 256>>>(row_v2u, col_u2v);

    split_k<<<4096, 256>>>(xe_e, XEH, XEL, (size_t)NE * 64);
    tsplit_k<<<512, 256>>>(W_v2u, DK, 256, WTUH, WTUL);
    tsplit_k<<<512, 256>>>(W_u2v, DK, 256, WTVH, WTVL);

    // aggregation, both directions in one launch
    agg_k<<<2 * NU, 256>>>(
        off_u, eid_u, col_v2u, wv, xvs, xe_v2u, xut, AHU, ALU,
        off_v, eid_v, row_u2v, wu, xus, xe_u2v, xvt, AHV, ALV);

    // node GEMMs, merged (z = u/v, y = 4 n-blocks of 64), fused BN stats
    gemm_bf3<<<dim3(157, 4, 2), 256, SMEM_G>>>(
        AHU, ALU, WTUH, WTUL, out_u,
        AHV, ALV, WTVH, WTVL, out_v,
        DK, DK, 256, NU, DK,
        nullptr, nullptr, nullptr, nullptr,
        sum_u, ssq_u, sum_v, ssq_v);
    // edge GEMM + fused combine + fused BN stats
    gemm_bf3<<<dim3(NE / 128, 1, 1), 256, SMEM_G>>>(
        XEH, XEL, WTEH, WTEL, out_e,
        XEH, XEL, WTEH, WTEL, out_e,
        64, 576, 64, NE, 64,
        pu, pv, row_e, col_e,
        sum_e, ssq_e, sum_e, ssq_e);

    // BN finalize + single fused apply pass
    bnfin_all<<<3, 256>>>(g_v2u, be_v2u, g_u2v, be_u2v, g_e, be_e);
    bnapply_all<<<4096, 256>>>(out_u, out_v, out_e);
}